// round 1
// baseline (speedup 1.0000x reference)
#include <cuda_runtime.h>
#include <cuda_bf16.h>

// Problem constants (hardcoded; scalar inputs num_of_projection/bins ignored)
#define S_ROWS 16384
#define K_DIM  1024
#define D_TOT  6400
#define BINS   20

#define BM 128
#define BN 128
#define BK 16
#define NTHREADS 256
#define BMP (BM + 4)   // padded row stride (132 floats = 528B, 16B-aligned)
#define BNP (BN + 4)

// Global scratch histogram (counts as float, exact for counts <= 16384)
__device__ float g_hist[D_TOT * BINS];

__global__ void zero_hist_kernel() {
    int i = blockIdx.x * blockDim.x + threadIdx.x;
    if (i < D_TOT * BINS) g_hist[i] = 0.0f;
}

__global__ __launch_bounds__(NTHREADS, 2)
void gemm_hist_kernel(const float* __restrict__ x,
                      const float* __restrict__ W,
                      const float* __restrict__ mins,
                      const float* __restrict__ maxs)
{
    __shared__ float As[2][BK][BMP];
    __shared__ float Bs[2][BK][BNP];
    __shared__ float hist_s[BN][BINS];
    __shared__ float mn_s[BN], mx_s[BN], sc_s[BN];

    const int tid = threadIdx.x;
    const int tx = tid & 15;        // 0..15  -> N direction
    const int ty = tid >> 4;        // 0..15  -> M direction
    const int m0 = blockIdx.y * BM;
    const int n0 = blockIdx.x * BN;

    // init smem histogram + per-column min/max/scale
    #pragma unroll
    for (int i = tid; i < BN * BINS; i += NTHREADS)
        (&hist_s[0][0])[i] = 0.0f;
    if (tid < BN) {
        float mn = mins[n0 + tid];
        float mx = maxs[n0 + tid];
        mn_s[tid] = mn;
        mx_s[tid] = mx;
        sc_s[tid] = (float)BINS / (mx - mn);
    }

    // ---- load k-tile 0 into buffer 0 ----
    {
        #pragma unroll
        for (int i = 0; i < 2; ++i) {
            int e  = tid + NTHREADS * i;      // float4 index, 0..511
            int r  = e >> 2;
            int c4 = e & 3;
            float4 va = *(const float4*)(x + (size_t)(m0 + r) * K_DIM + c4 * 4);
            As[0][c4 * 4 + 0][r] = va.x;
            As[0][c4 * 4 + 1][r] = va.y;
            As[0][c4 * 4 + 2][r] = va.z;
            As[0][c4 * 4 + 3][r] = va.w;
            float4 vb = *(const float4*)(W + (size_t)(n0 + r) * K_DIM + c4 * 4);
            Bs[0][c4 * 4 + 0][r] = vb.x;
            Bs[0][c4 * 4 + 1][r] = vb.y;
            Bs[0][c4 * 4 + 2][r] = vb.z;
            Bs[0][c4 * 4 + 3][r] = vb.w;
        }
    }
    __syncthreads();

    float acc[8][8];
    #pragma unroll
    for (int i = 0; i < 8; ++i)
        #pragma unroll
        for (int j = 0; j < 8; ++j) acc[i][j] = 0.0f;

    int buf = 0;
    const int NKT = K_DIM / BK;
    for (int kt = 0; kt < NKT; ++kt) {
        // prefetch next k-tile into registers
        float4 pa[2], pb[2];
        const int knext = (kt + 1) * BK;
        if (kt + 1 < NKT) {
            #pragma unroll
            for (int i = 0; i < 2; ++i) {
                int e  = tid + NTHREADS * i;
                int r  = e >> 2;
                int c4 = e & 3;
                pa[i] = *(const float4*)(x + (size_t)(m0 + r) * K_DIM + knext + c4 * 4);
                pb[i] = *(const float4*)(W + (size_t)(n0 + r) * K_DIM + knext + c4 * 4);
            }
        }

        // compute on current buffer
        const float* Ab = &As[buf][0][ty * 8];
        const float* Bb = &Bs[buf][0][tx * 8];
        #pragma unroll
        for (int kk = 0; kk < BK; ++kk) {
            float4 a0 = *(const float4*)(Ab + kk * BMP);
            float4 a1 = *(const float4*)(Ab + kk * BMP + 4);
            float4 b0 = *(const float4*)(Bb + kk * BNP);
            float4 b1 = *(const float4*)(Bb + kk * BNP + 4);
            float ar[8] = {a0.x, a0.y, a0.z, a0.w, a1.x, a1.y, a1.z, a1.w};
            float br[8] = {b0.x, b0.y, b0.z, b0.w, b1.x, b1.y, b1.z, b1.w};
            #pragma unroll
            for (int i = 0; i < 8; ++i)
                #pragma unroll
                for (int j = 0; j < 8; ++j)
                    acc[i][j] = fmaf(ar[i], br[j], acc[i][j]);
        }

        // store prefetched tile to other buffer
        if (kt + 1 < NKT) {
            int ob = buf ^ 1;
            #pragma unroll
            for (int i = 0; i < 2; ++i) {
                int e  = tid + NTHREADS * i;
                int r  = e >> 2;
                int c4 = e & 3;
                As[ob][c4 * 4 + 0][r] = pa[i].x;
                As[ob][c4 * 4 + 1][r] = pa[i].y;
                As[ob][c4 * 4 + 2][r] = pa[i].z;
                As[ob][c4 * 4 + 3][r] = pa[i].w;
                Bs[ob][c4 * 4 + 0][r] = pb[i].x;
                Bs[ob][c4 * 4 + 1][r] = pb[i].y;
                Bs[ob][c4 * 4 + 2][r] = pb[i].z;
                Bs[ob][c4 * 4 + 3][r] = pb[i].w;
            }
        }
        __syncthreads();
        buf ^= 1;
    }

    // ---- histogram epilogue: bin this tile's 128x128 projections into smem ----
    #pragma unroll
    for (int j = 0; j < 8; ++j) {
        int c = tx * 8 + j;
        float mn = mn_s[c];
        float mx = mx_s[c];
        float sc = sc_s[c];
        #pragma unroll
        for (int i = 0; i < 8; ++i) {
            float p = acc[i][j];
            if (p >= mn && p <= mx) {
                int b = (int)((p - mn) * sc);   // >= 0 since p >= mn
                b = min(b, BINS - 1);
                atomicAdd(&hist_s[c][b], 1.0f);
            }
        }
    }
    __syncthreads();

    // flush smem histogram to global (skip zeros to cut atomics)
    for (int i = tid; i < BN * BINS; i += NTHREADS) {
        float v = (&hist_s[0][0])[i];
        if (v != 0.0f)
            atomicAdd(&g_hist[(size_t)n0 * BINS + i], v);
    }
}

// L2-normalize each group of BINS values; one warp per projected dim.
__global__ void normalize_kernel(float* __restrict__ out)
{
    int row  = blockIdx.x * 4 + (threadIdx.x >> 5);
    int lane = threadIdx.x & 31;
    if (row >= D_TOT) return;
    float v = (lane < BINS) ? g_hist[row * BINS + lane] : 0.0f;
    float s = v * v;
    #pragma unroll
    for (int o = 16; o; o >>= 1) s += __shfl_xor_sync(0xFFFFFFFFu, s, o);
    float denom = fmaxf(sqrtf(s), 1e-12f);
    if (lane < BINS) out[row * BINS + lane] = v / denom;
}

extern "C" void kernel_launch(void* const* d_in, const int* in_sizes, int n_in,
                              void* d_out, int out_size)
{
    const float* x    = (const float*)d_in[0];
    const float* W    = (const float*)d_in[1];
    const float* mins = (const float*)d_in[2];
    const float* maxs = (const float*)d_in[3];
    float* out = (float*)d_out;

    zero_hist_kernel<<<(D_TOT * BINS + 255) / 256, 256>>>();

    dim3 grid(D_TOT / BN, S_ROWS / BM);   // (50, 128)
    gemm_hist_kernel<<<grid, NTHREADS>>>(x, W, mins, maxs);

    normalize_kernel<<<(D_TOT + 3) / 4, 128>>>(out);
}

// round 3
// speedup vs baseline: 2.0269x; 2.0269x over previous
#include <cuda_runtime.h>
#include <cuda_bf16.h>
#include <cstdint>

// ---------------- problem constants ----------------
#define S_ROWS 16384
#define K_DIM  1024
#define D_TOT  6400
#define BINS   20

// ---------------- tiling ----------------
#define BM 128
#define BN 128
#define BK 64
#define STAGES 3
#define KT (K_DIM / BK)          // 16
#define NTHREADS 256             // 8 warps: 2 (M) x 4 (N), warp tile 64x32

#define PLANE_B 16384            // 128 rows x 64 bf16 = 16KB per plane tile
#define STAGE_B (4 * PLANE_B)    // Ahi, Alo, Bhi, Blo
#define OFF_META (STAGES * STAGE_B)          // 196608
#define SMEM_TOTAL (OFF_META + 3 * BN * 4)   // + mn/mx/sc

// ---------------- global scratch ----------------
__device__ __nv_bfloat16 g_xhi[S_ROWS * K_DIM];
__device__ __nv_bfloat16 g_xlo[S_ROWS * K_DIM];
__device__ __nv_bfloat16 g_whi[D_TOT * K_DIM];
__device__ __nv_bfloat16 g_wlo[D_TOT * K_DIM];
__device__ float g_hist[D_TOT * BINS];

// ---------------- helpers ----------------
__device__ __forceinline__ uint32_t smem_u32(const void* p) {
    uint32_t a;
    asm("{ .reg .u64 t; cvta.to.shared.u64 t, %1; cvt.u32.u64 %0, t; }"
        : "=r"(a) : "l"(p));
    return a;
}
__device__ __forceinline__ uint32_t sw128(uint32_t off) {
    return off ^ ((off >> 3) & 0x70);
}
__device__ __forceinline__ void cp16(uint32_t s, const void* g) {
    asm volatile("cp.async.cg.shared.global [%0], [%1], 16;" :: "r"(s), "l"(g));
}
#define CP_COMMIT() asm volatile("cp.async.commit_group;" ::: "memory")
#define CP_WAIT(n)  asm volatile("cp.async.wait_group %0;" :: "n"(n) : "memory")

__device__ __forceinline__ void ldsm4(uint32_t* r, uint32_t addr) {
    asm volatile("ldmatrix.sync.aligned.m8n8.x4.shared.b16 {%0,%1,%2,%3}, [%4];"
        : "=r"(r[0]), "=r"(r[1]), "=r"(r[2]), "=r"(r[3]) : "r"(addr));
}
__device__ __forceinline__ void mma_bf16(float* d, const uint32_t* a,
                                         uint32_t b0, uint32_t b1) {
    asm volatile(
        "mma.sync.aligned.m16n8k16.row.col.f32.bf16.bf16.f32 "
        "{%0,%1,%2,%3}, {%4,%5,%6,%7}, {%8,%9}, {%0,%1,%2,%3};"
        : "+f"(d[0]), "+f"(d[1]), "+f"(d[2]), "+f"(d[3])
        : "r"(a[0]), "r"(a[1]), "r"(a[2]), "r"(a[3]), "r"(b0), "r"(b1));
}

// ---------------- pre-split: fp32 -> bf16 hi/lo planes ----------------
__global__ void split_kernel(const float4* __restrict__ src,
                             uint2* __restrict__ hi, uint2* __restrict__ lo, int n4)
{
    int i = blockIdx.x * blockDim.x + threadIdx.x;
    if (i >= n4) return;
    float4 v = src[i];
    uint32_t h0, h1, g0, g1;
    asm("cvt.rn.bf16x2.f32 %0, %1, %2;" : "=r"(h0) : "f"(v.y), "f"(v.x));
    asm("cvt.rn.bf16x2.f32 %0, %1, %2;" : "=r"(h1) : "f"(v.w), "f"(v.z));
    float l0 = v.x - __uint_as_float(h0 << 16);
    float l1 = v.y - __uint_as_float(h0 & 0xFFFF0000u);
    float l2 = v.z - __uint_as_float(h1 << 16);
    float l3 = v.w - __uint_as_float(h1 & 0xFFFF0000u);
    asm("cvt.rn.bf16x2.f32 %0, %1, %2;" : "=r"(g0) : "f"(l1), "f"(l0));
    asm("cvt.rn.bf16x2.f32 %0, %1, %2;" : "=r"(g1) : "f"(l3), "f"(l2));
    hi[i] = make_uint2(h0, h1);
    lo[i] = make_uint2(g0, g1);
}

__global__ void zero_hist_kernel() {
    int i = blockIdx.x * blockDim.x + threadIdx.x;
    if (i < D_TOT * BINS) g_hist[i] = 0.0f;
}

// ---------------- fused GEMM + histogram ----------------
__global__ __launch_bounds__(NTHREADS, 1)
void gemm_hist_kernel(const float* __restrict__ mins, const float* __restrict__ maxs)
{
    extern __shared__ char smem[];
    const uint32_t sb = smem_u32(smem);
    const int tid  = threadIdx.x;
    const int wid  = tid >> 5;
    const int lane = tid & 31;
    const int wm = wid & 1;          // warp M index (0..1)
    const int wn = wid >> 1;         // warp N index (0..3)

    const int m0  = blockIdx.y * BM;
    const int n0t = blockIdx.x * BN;

    const __nv_bfloat16* Ah = g_xhi + (size_t)m0 * K_DIM;
    const __nv_bfloat16* Al = g_xlo + (size_t)m0 * K_DIM;
    const __nv_bfloat16* Bh = g_whi + (size_t)n0t * K_DIM;
    const __nv_bfloat16* Bl = g_wlo + (size_t)n0t * K_DIM;

    float* mnS = (float*)(smem + OFF_META);
    float* mxS = mnS + BN;
    float* scS = mxS + BN;
    if (tid < BN) {
        float mn = mins[n0t + tid], mx = maxs[n0t + tid];
        mnS[tid] = mn; mxS[tid] = mx;
        scS[tid] = (float)BINS / (mx - mn);
    }

    // per-thread loader geometry
    const int lrow = tid >> 3;       // base row (0..31), +32*i
    const int lcol = tid & 7;        // 16B chunk in 128B row

    auto load_stage = [&](int kt) {
        const uint32_t st = sb + (uint32_t)((kt % STAGES) * STAGE_B);
        #pragma unroll
        for (int i = 0; i < 4; ++i) {
            int row = lrow + 32 * i;
            uint32_t soff = sw128((uint32_t)(row * 128 + lcol * 16));
            size_t go = (size_t)row * K_DIM + (size_t)kt * BK + lcol * 8;
            cp16(st + 0 * PLANE_B + soff, Ah + go);
            cp16(st + 1 * PLANE_B + soff, Al + go);
            cp16(st + 2 * PLANE_B + soff, Bh + go);
            cp16(st + 3 * PLANE_B + soff, Bl + go);
        }
    };

    float acc[4][4][4];
    #pragma unroll
    for (int i = 0; i < 4; ++i)
        #pragma unroll
        for (int j = 0; j < 4; ++j)
            #pragma unroll
            for (int r = 0; r < 4; ++r) acc[i][j][r] = 0.0f;

    load_stage(0); CP_COMMIT();
    load_stage(1); CP_COMMIT();

    const int l15  = lane & 15;
    const int khalf = (lane >> 4) << 4;   // byte offset for k-half (0 or 16)

    for (int kt = 0; kt < KT; ++kt) {
        if (kt + 2 < KT) load_stage(kt + 2);
        CP_COMMIT();
        CP_WAIT(2);
        __syncthreads();

        const uint32_t st = sb + (uint32_t)((kt % STAGES) * STAGE_B);
        #pragma unroll
        for (int ks = 0; ks < BK / 16; ++ks) {
            uint32_t af[2][4][4];
            #pragma unroll
            for (int p = 0; p < 2; ++p)
                #pragma unroll
                for (int mf = 0; mf < 4; ++mf) {
                    int arow = wm * 64 + mf * 16 + l15;
                    uint32_t off = (uint32_t)(arow * 128 + ks * 32) + khalf;
                    ldsm4(af[p][mf], st + p * PLANE_B + sw128(off));
                }
            uint32_t bfr[2][2][4];
            #pragma unroll
            for (int p = 0; p < 2; ++p)
                #pragma unroll
                for (int ng = 0; ng < 2; ++ng) {
                    int nrow = wn * 32 + ng * 16 + l15;
                    uint32_t off = (uint32_t)(nrow * 128 + ks * 32) + khalf;
                    ldsm4(bfr[p][ng], st + (2 + p) * PLANE_B + sw128(off));
                }
            // frag for n-first-8 of a 16-group: {r0,r2}; n-second-8: {r1,r3}
            #pragma unroll
            for (int mf = 0; mf < 4; ++mf)
                #pragma unroll
                for (int nf = 0; nf < 4; ++nf) {
                    int ng = nf >> 1, h = nf & 1;
                    mma_bf16(acc[mf][nf], af[0][mf], bfr[0][ng][h], bfr[0][ng][2 + h]);
                    mma_bf16(acc[mf][nf], af[0][mf], bfr[1][ng][h], bfr[1][ng][2 + h]);
                    mma_bf16(acc[mf][nf], af[1][mf], bfr[0][ng][h], bfr[0][ng][2 + h]);
                }
        }
        __syncthreads();
    }
    CP_WAIT(0);
    __syncthreads();

    // ---------------- histogram epilogue ----------------
    float* hall = (float*)smem;                 // 8 warp copies x 128 cols x 20 bins
    for (int i = tid; i < 8 * BN * BINS; i += NTHREADS) hall[i] = 0.0f;
    __syncthreads();

    float* hw = hall + wid * (BN * BINS);
    const int q = lane & 3;
    #pragma unroll
    for (int nf = 0; nf < 4; ++nf) {
        #pragma unroll
        for (int half = 0; half < 2; ++half) {
            int c = wn * 32 + nf * 8 + 2 * q + half;
            float mn = mnS[c], mx = mxS[c], sc = scS[c];
            #pragma unroll
            for (int mf = 0; mf < 4; ++mf)
                #pragma unroll
                for (int rp = 0; rp < 2; ++rp) {
                    float p = acc[mf][nf][2 * rp + half];
                    if (p >= mn && p <= mx) {
                        int b = min((int)((p - mn) * sc), BINS - 1);
                        atomicAdd(&hw[c * BINS + b], 1.0f);
                    }
                }
        }
    }
    __syncthreads();

    for (int i = tid; i < BN * BINS; i += NTHREADS) {
        float s = 0.0f;
        #pragma unroll
        for (int w = 0; w < 8; ++w) s += hall[w * (BN * BINS) + i];
        if (s != 0.0f)
            atomicAdd(&g_hist[(size_t)n0t * BINS + i], s);
    }
}

// ---------------- normalize ----------------
__global__ void normalize_kernel(float* __restrict__ out)
{
    int row  = blockIdx.x * 4 + (threadIdx.x >> 5);
    int lane = threadIdx.x & 31;
    if (row >= D_TOT) return;
    float v = (lane < BINS) ? g_hist[row * BINS + lane] : 0.0f;
    float s = v * v;
    #pragma unroll
    for (int o = 16; o; o >>= 1) s += __shfl_xor_sync(0xFFFFFFFFu, s, o);
    float denom = fmaxf(sqrtf(s), 1e-12f);
    if (lane < BINS) out[row * BINS + lane] = v / denom;
}

extern "C" void kernel_launch(void* const* d_in, const int* in_sizes, int n_in,
                              void* d_out, int out_size)
{
    const float* x    = (const float*)d_in[0];
    const float* W    = (const float*)d_in[1];
    const float* mins = (const float*)d_in[2];
    const float* maxs = (const float*)d_in[3];
    float* out = (float*)d_out;

    static int attr_set = 0;
    if (!attr_set) {
        cudaFuncSetAttribute(gemm_hist_kernel,
                             cudaFuncAttributeMaxDynamicSharedMemorySize, SMEM_TOTAL);
        attr_set = 1;
    }

    __nv_bfloat16 *xhi, *xlo, *whi, *wlo;
    cudaGetSymbolAddress((void**)&xhi, g_xhi);
    cudaGetSymbolAddress((void**)&xlo, g_xlo);
    cudaGetSymbolAddress((void**)&whi, g_whi);
    cudaGetSymbolAddress((void**)&wlo, g_wlo);

    int nx4 = S_ROWS * K_DIM / 4;
    int nw4 = D_TOT * K_DIM / 4;
    split_kernel<<<(nx4 + 255) / 256, 256>>>((const float4*)x, (uint2*)xhi, (uint2*)xlo, nx4);
    split_kernel<<<(nw4 + 255) / 256, 256>>>((const float4*)W, (uint2*)whi, (uint2*)wlo, nw4);
    zero_hist_kernel<<<(D_TOT * BINS + 255) / 256, 256>>>();

    dim3 grid(D_TOT / BN, S_ROWS / BM);   // (50, 128)
    gemm_hist_kernel<<<grid, NTHREADS, SMEM_TOTAL>>>(mins, maxs);

    normalize_kernel<<<(D_TOT + 3) / 4, 128>>>(out);
}

// round 6
// speedup vs baseline: 2.2616x; 1.1158x over previous
#include <cuda_runtime.h>
#include <cuda_bf16.h>
#include <cstdint>

// ---------------- problem constants ----------------
#define S_ROWS 16384
#define K_DIM  1024
#define D_TOT  6400
#define BINS   20

// ---------------- tiling ----------------
#define BM 128
#define BN 128
#define BK 64
#define STAGES 3
#define KT (K_DIM / BK)          // 16
#define NTHREADS 512             // 16 warps: 4 (M) x 4 (N), warp tile 32x32

#define PLANE_B 16384            // 128 rows x 64 bf16 = 16KB per plane tile
#define STAGE_B (4 * PLANE_B)    // Ahi, Alo, Bhi, Blo
#define OFF_META (STAGES * STAGE_B)          // 196608
#define SMEM_TOTAL (OFF_META + 3 * BN * 4)   // + mn/mx/sc

// ---------------- global scratch ----------------
__device__ __nv_bfloat16 g_xhi[S_ROWS * K_DIM];
__device__ __nv_bfloat16 g_xlo[S_ROWS * K_DIM];
__device__ __nv_bfloat16 g_whi[D_TOT * K_DIM];
__device__ __nv_bfloat16 g_wlo[D_TOT * K_DIM];
__device__ float g_hist[D_TOT * BINS];

// ---------------- helpers ----------------
__device__ __forceinline__ uint32_t smem_u32(const void* p) {
    uint32_t a;
    asm("{ .reg .u64 t; cvta.to.shared.u64 t, %1; cvt.u32.u64 %0, t; }"
        : "=r"(a) : "l"(p));
    return a;
}
__device__ __forceinline__ uint32_t sw128(uint32_t off) {
    return off ^ ((off >> 3) & 0x70);
}
__device__ __forceinline__ void cp16(uint32_t s, const void* g) {
    asm volatile("cp.async.cg.shared.global [%0], [%1], 16;" :: "r"(s), "l"(g));
}
#define CP_COMMIT() asm volatile("cp.async.commit_group;" ::: "memory")
#define CP_WAIT(n)  asm volatile("cp.async.wait_group %0;" :: "n"(n) : "memory")

__device__ __forceinline__ void ldsm4(uint32_t* r, uint32_t addr) {
    asm volatile("ldmatrix.sync.aligned.m8n8.x4.shared.b16 {%0,%1,%2,%3}, [%4];"
        : "=r"(r[0]), "=r"(r[1]), "=r"(r[2]), "=r"(r[3]) : "r"(addr));
}
__device__ __forceinline__ void mma_bf16(float* d, const uint32_t* a,
                                         uint32_t b0, uint32_t b1) {
    asm volatile(
        "mma.sync.aligned.m16n8k16.row.col.f32.bf16.bf16.f32 "
        "{%0,%1,%2,%3}, {%4,%5,%6,%7}, {%8,%9}, {%0,%1,%2,%3};"
        : "+f"(d[0]), "+f"(d[1]), "+f"(d[2]), "+f"(d[3])
        : "r"(a[0]), "r"(a[1]), "r"(a[2]), "r"(a[3]), "r"(b0), "r"(b1));
}

// ---------------- pre-split: fp32 -> bf16 hi/lo planes ----------------
__global__ void split_kernel(const float4* __restrict__ src,
                             uint2* __restrict__ hi, uint2* __restrict__ lo, int n4)
{
    int i = blockIdx.x * blockDim.x + threadIdx.x;
    if (i >= n4) return;
    float4 v = src[i];
    uint32_t h0, h1, g0, g1;
    asm("cvt.rn.bf16x2.f32 %0, %1, %2;" : "=r"(h0) : "f"(v.y), "f"(v.x));
    asm("cvt.rn.bf16x2.f32 %0, %1, %2;" : "=r"(h1) : "f"(v.w), "f"(v.z));
    float l0 = v.x - __uint_as_float(h0 << 16);
    float l1 = v.y - __uint_as_float(h0 & 0xFFFF0000u);
    float l2 = v.z - __uint_as_float(h1 << 16);
    float l3 = v.w - __uint_as_float(h1 & 0xFFFF0000u);
    asm("cvt.rn.bf16x2.f32 %0, %1, %2;" : "=r"(g0) : "f"(l1), "f"(l0));
    asm("cvt.rn.bf16x2.f32 %0, %1, %2;" : "=r"(g1) : "f"(l3), "f"(l2));
    hi[i] = make_uint2(h0, h1);
    lo[i] = make_uint2(g0, g1);
}

__global__ void zero_hist_kernel() {
    int i = blockIdx.x * blockDim.x + threadIdx.x;
    if (i < D_TOT * BINS) g_hist[i] = 0.0f;
}

// ---------------- fused GEMM + histogram ----------------
__global__ __launch_bounds__(NTHREADS, 1)
void gemm_hist_kernel(const float* __restrict__ mins, const float* __restrict__ maxs)
{
    extern __shared__ char smem[];
    const uint32_t sb = smem_u32(smem);
    const int tid  = threadIdx.x;
    const int wid  = tid >> 5;
    const int lane = tid & 31;
    const int wm = wid & 3;          // warp M index (0..3)
    const int wn = wid >> 2;         // warp N index (0..3)

    const int m0  = blockIdx.y * BM;
    const int n0t = blockIdx.x * BN;

    const __nv_bfloat16* Ah = g_xhi + (size_t)m0 * K_DIM;
    const __nv_bfloat16* Al = g_xlo + (size_t)m0 * K_DIM;
    const __nv_bfloat16* Bh = g_whi + (size_t)n0t * K_DIM;
    const __nv_bfloat16* Bl = g_wlo + (size_t)n0t * K_DIM;

    float* mnS = (float*)(smem + OFF_META);
    float* mxS = mnS + BN;
    float* scS = mxS + BN;
    if (tid < BN) {
        float mn = mins[n0t + tid], mx = maxs[n0t + tid];
        mnS[tid] = mn; mxS[tid] = mx;
        scS[tid] = (float)BINS / (mx - mn);
    }

    // per-thread loader geometry: 512 threads, 2 rows per plane each
    const int lrow = tid >> 3;       // base row (0..63), +64*i
    const int lcol = tid & 7;        // 16B chunk in 128B row

    auto load_stage = [&](int kt) {
        const uint32_t st = sb + (uint32_t)((kt % STAGES) * STAGE_B);
        #pragma unroll
        for (int i = 0; i < 2; ++i) {
            int row = lrow + 64 * i;
            uint32_t soff = sw128((uint32_t)(row * 128 + lcol * 16));
            size_t go = (size_t)row * K_DIM + (size_t)kt * BK + lcol * 8;
            cp16(st + 0 * PLANE_B + soff, Ah + go);
            cp16(st + 1 * PLANE_B + soff, Al + go);
            cp16(st + 2 * PLANE_B + soff, Bh + go);
            cp16(st + 3 * PLANE_B + soff, Bl + go);
        }
    };

    float acc[2][4][4];
    #pragma unroll
    for (int i = 0; i < 2; ++i)
        #pragma unroll
        for (int j = 0; j < 4; ++j)
            #pragma unroll
            for (int r = 0; r < 4; ++r) acc[i][j][r] = 0.0f;

    load_stage(0); CP_COMMIT();
    load_stage(1); CP_COMMIT();

    const int l15  = lane & 15;
    const int khalf = (lane >> 4) << 4;   // byte offset for k-half (0 or 16)

    for (int kt = 0; kt < KT; ++kt) {
        if (kt + 2 < KT) load_stage(kt + 2);
        CP_COMMIT();
        CP_WAIT(2);
        __syncthreads();

        const uint32_t st = sb + (uint32_t)((kt % STAGES) * STAGE_B);
        #pragma unroll
        for (int ks = 0; ks < BK / 16; ++ks) {
            uint32_t af[2][2][4];
            #pragma unroll
            for (int p = 0; p < 2; ++p)
                #pragma unroll
                for (int mf = 0; mf < 2; ++mf) {
                    int arow = wm * 32 + mf * 16 + l15;
                    uint32_t off = (uint32_t)(arow * 128 + ks * 32) + khalf;
                    ldsm4(af[p][mf], st + p * PLANE_B + sw128(off));
                }
            uint32_t bfr[2][2][4];
            #pragma unroll
            for (int p = 0; p < 2; ++p)
                #pragma unroll
                for (int ng = 0; ng < 2; ++ng) {
                    int nrow = wn * 32 + ng * 16 + l15;
                    uint32_t off = (uint32_t)(nrow * 128 + ks * 32) + khalf;
                    ldsm4(bfr[p][ng], st + (2 + p) * PLANE_B + sw128(off));
                }
            // frag for n-first-8 of a 16-group: {r0,r2}; n-second-8: {r1,r3}
            #pragma unroll
            for (int mf = 0; mf < 2; ++mf)
                #pragma unroll
                for (int nf = 0; nf < 4; ++nf) {
                    int ng = nf >> 1, h = nf & 1;
                    mma_bf16(acc[mf][nf], af[0][mf], bfr[0][ng][h], bfr[0][ng][2 + h]);
                    mma_bf16(acc[mf][nf], af[0][mf], bfr[1][ng][h], bfr[1][ng][2 + h]);
                    mma_bf16(acc[mf][nf], af[1][mf], bfr[0][ng][h], bfr[0][ng][2 + h]);
                }
        }
        __syncthreads();
    }
    CP_WAIT(0);
    __syncthreads();

    // ---------------- histogram epilogue ----------------
    float* hall = (float*)smem;                 // 16 warp copies x 128 cols x 20 bins
    for (int i = tid; i < 16 * BN * BINS; i += NTHREADS) hall[i] = 0.0f;
    __syncthreads();

    float* hw = hall + wid * (BN * BINS);
    const int q = lane & 3;
    #pragma unroll
    for (int nf = 0; nf < 4; ++nf) {
        #pragma unroll
        for (int half = 0; half < 2; ++half) {
            int c = wn * 32 + nf * 8 + 2 * q + half;
            float mn = mnS[c], mx = mxS[c], sc = scS[c];
            #pragma unroll
            for (int mf = 0; mf < 2; ++mf)
                #pragma unroll
                for (int rp = 0; rp < 2; ++rp) {
                    float p = acc[mf][nf][2 * rp + half];
                    if (p >= mn && p <= mx) {
                        int b = min((int)((p - mn) * sc), BINS - 1);
                        atomicAdd(&hw[c * BINS + b], 1.0f);
                    }
                }
        }
    }
    __syncthreads();

    for (int i = tid; i < BN * BINS; i += NTHREADS) {
        float s = 0.0f;
        #pragma unroll
        for (int w = 0; w < 16; ++w) s += hall[w * (BN * BINS) + i];
        if (s != 0.0f)
            atomicAdd(&g_hist[(size_t)n0t * BINS + i], s);
    }
}

// ---------------- normalize ----------------
__global__ void normalize_kernel(float* __restrict__ out)
{
    int row  = blockIdx.x * 4 + (threadIdx.x >> 5);
    int lane = threadIdx.x & 31;
    if (row >= D_TOT) return;
    float v = (lane < BINS) ? g_hist[row * BINS + lane] : 0.0f;
    float s = v * v;
    #pragma unroll
    for (int o = 16; o; o >>= 1) s += __shfl_xor_sync(0xFFFFFFFFu, s, o);
    float denom = fmaxf(sqrtf(s), 1e-12f);
    if (lane < BINS) out[row * BINS + lane] = v / denom;
}

extern "C" void kernel_launch(void* const* d_in, const int* in_sizes, int n_in,
                              void* d_out, int out_size)
{
    const float* x    = (const float*)d_in[0];
    const float* W    = (const float*)d_in[1];
    const float* mins = (const float*)d_in[2];
    const float* maxs = (const float*)d_in[3];
    float* out = (float*)d_out;

    static int attr_set = 0;
    if (!attr_set) {
        cudaFuncSetAttribute(gemm_hist_kernel,
                             cudaFuncAttributeMaxDynamicSharedMemorySize, SMEM_TOTAL);
        attr_set = 1;
    }

    __nv_bfloat16 *xhi, *xlo, *whi, *wlo;
    cudaGetSymbolAddress((void**)&xhi, g_xhi);
    cudaGetSymbolAddress((void**)&xlo, g_xlo);
    cudaGetSymbolAddress((void**)&whi, g_whi);
    cudaGetSymbolAddress((void**)&wlo, g_wlo);

    int nx4 = S_ROWS * K_DIM / 4;
    int nw4 = D_TOT * K_DIM / 4;
    split_kernel<<<(nx4 + 255) / 256, 256>>>((const float4*)x, (uint2*)xhi, (uint2*)xlo, nx4);
    split_kernel<<<(nw4 + 255) / 256, 256>>>((const float4*)W, (uint2*)whi, (uint2*)wlo, nw4);
    zero_hist_kernel<<<(D_TOT * BINS + 255) / 256, 256>>>();

    dim3 grid(D_TOT / BN, S_ROWS / BM);   // (50, 128)
    gemm_hist_kernel<<<grid, NTHREADS, SMEM_TOTAL>>>(mins, maxs);

    normalize_kernel<<<(D_TOT + 3) / 4, 128>>>(out);
}